// round 14
// baseline (speedup 1.0000x reference)
#include <cuda_runtime.h>
#include <cuda_bf16.h>
#include <cuda_fp16.h>
#include <math.h>
#include <stdint.h>

// ---------------------------------------------------------------------------
// TransformerBlock on GB300 (sm_103a via compute_103 PTX).
// GEMMs: mma.sync m16n8k16 bf16 hi/lo-split (3-product), fp32 accumulate.
// Attention: mma.sync f16 flash (f16 Q/K/V, log2-domain softmax, f16x2 exp,
//            P kept in registers as PV A-fragments, V^T via ldmatrix.trans).
// ---------------------------------------------------------------------------

#define NTOK   4096   // B*S
#define DM     1024
#define DFF_   4096
#define SEQ    2048
#define NH     16
#define HD     64

typedef __nv_bfloat16 bf16;

extern __shared__ char dynsm[];   // single dynamic-smem symbol for all kernels

// ------------------------------- scratch ----------------------------------
__device__ __align__(256) float g_res1[NTOK * DM];
__device__ __align__(256) float g_out1[NTOK * DM];
__device__ __align__(256) float g_res2[NTOK * DM];

__device__ __align__(256) __half g_qf[NTOK * DM];
__device__ __align__(256) __half g_kf[NTOK * DM];
__device__ __align__(256) __half g_vf[NTOK * DM];

__device__ __align__(256) bf16 g_xh [NTOK * DM],   g_xl [NTOK * DM];
__device__ __align__(256) bf16 g_ch [NTOK * DM],   g_cl [NTOK * DM];   // ctx
__device__ __align__(256) bf16 g_o1h[NTOK * DM],   g_o1l[NTOK * DM];   // out1
__device__ __align__(256) bf16 g_hh [NTOK * DFF_], g_hl [NTOK * DFF_]; // hid
__device__ __align__(256) bf16 g_wqh[DM * DM],   g_wql[DM * DM];
__device__ __align__(256) bf16 g_wkh[DM * DM],   g_wkl[DM * DM];
__device__ __align__(256) bf16 g_wvh[DM * DM],   g_wvl[DM * DM];
__device__ __align__(256) bf16 g_woh[DM * DM],   g_wol[DM * DM];
__device__ __align__(256) bf16 g_w1h[DFF_ * DM], g_w1l[DFF_ * DM];
__device__ __align__(256) bf16 g_w2h[DM * DFF_], g_w2l[DM * DFF_];

// --------------------------- device helpers --------------------------------
__device__ __forceinline__ uint32_t smem_u32(const void* p) {
    uint32_t a;
    asm("{ .reg .u64 t; cvta.to.shared.u64 t, %1; cvt.u32.u64 %0, t; }" : "=r"(a) : "l"(p));
    return a;
}
__device__ __forceinline__ uint32_t lds_b32(uint32_t addr) {
    uint32_t v;
    asm volatile("ld.shared.b32 %0, [%1];" : "=r"(v) : "r"(addr));
    return v;
}
__device__ __forceinline__ void cp16(uint32_t dst, const void* src) {
    asm volatile("cp.async.cg.shared.global [%0], [%1], 16;" :: "r"(dst), "l"(src) : "memory");
}
__device__ __forceinline__ void cp_commit() {
    asm volatile("cp.async.commit_group;" ::: "memory");
}
__device__ __forceinline__ void mma_bf16(float* d, const uint32_t* a, const uint32_t* b) {
    asm volatile(
        "mma.sync.aligned.m16n8k16.row.col.f32.bf16.bf16.f32 "
        "{%0,%1,%2,%3}, {%4,%5,%6,%7}, {%8,%9}, {%0,%1,%2,%3};"
        : "+f"(d[0]), "+f"(d[1]), "+f"(d[2]), "+f"(d[3])
        : "r"(a[0]), "r"(a[1]), "r"(a[2]), "r"(a[3]), "r"(b[0]), "r"(b[1]));
}
__device__ __forceinline__ void mma_f16(float* d, const uint32_t* a, const uint32_t* b) {
    asm volatile(
        "mma.sync.aligned.m16n8k16.row.col.f32.f16.f16.f32 "
        "{%0,%1,%2,%3}, {%4,%5,%6,%7}, {%8,%9}, {%0,%1,%2,%3};"
        : "+f"(d[0]), "+f"(d[1]), "+f"(d[2]), "+f"(d[3])
        : "r"(a[0]), "r"(a[1]), "r"(a[2]), "r"(a[3]), "r"(b[0]), "r"(b[1]));
}

// ---------------------------------------------------------------------------
// GEMM: C[M,N] = (Ah+Al)[M,K] @ (Bh+Bl)[N,K]^T + bias (+relu/+residual)
// 128x128 tile, BK=32, 256 threads (2x4 warps), warp tile 64x32.
// EPI: 0=bias, 1=bias+relu, 2=bias+residual.
// OUT: 0=f32 to C, 1=bf16 hi/lo to Oh/Ol, 2=f16 to (half*)Oh.
// ---------------------------------------------------------------------------
#define PADK 40
#define TILE_ELE (128 * PADK)
#define STAGE_ELE (4 * TILE_ELE)
#define GEMM_SMEM_BYTES (2 * STAGE_ELE * 2)   // 81920 B

template<int EPI, int OUT>
__global__ __launch_bounds__(256, 2)
void gemm_mma(const bf16* __restrict__ Ah, const bf16* __restrict__ Al,
              const bf16* __restrict__ Bh, const bf16* __restrict__ Bl,
              const float* __restrict__ bias, const float* __restrict__ R,
              float* __restrict__ C, bf16* __restrict__ Oh, bf16* __restrict__ Ol,
              int M, int N, int K)
{
    const uint32_t smBase = smem_u32(dynsm);

    const int tid  = threadIdx.x;
    const int lane = tid & 31, warp = tid >> 5;
    const int wm = warp >> 2, wn = warp & 3;
    const int gid = lane >> 2, tig = lane & 3;
    const int bx = blockIdx.x, by = blockIdx.y;

    const bf16* src[4] = { Ah + (size_t)by * 128 * K, Al + (size_t)by * 128 * K,
                           Bh + (size_t)bx * 128 * K, Bl + (size_t)bx * 128 * K };

    float acc[4][4][4];
    #pragma unroll
    for (int i = 0; i < 4; i++)
        #pragma unroll
        for (int j = 0; j < 4; j++)
            #pragma unroll
            for (int h = 0; h < 4; h++) acc[i][j][h] = 0.0f;

    const int nch = K >> 5;

    auto issue_loads = [&](int ch, int s) {
        const int kof = ch << 5;
        const uint32_t stage = smBase + (uint32_t)s * (STAGE_ELE * 2);
        #pragma unroll
        for (int i = 0; i < 8; i++) {
            const int c = tid + (i << 8);
            const int tile = c >> 9, w = c & 511, row = w >> 2, q = w & 3;
            const bf16* g = src[tile] + (size_t)row * K + kof + q * 8;
            const uint32_t d = stage + (uint32_t)(tile * TILE_ELE + row * PADK + q * 8) * 2;
            cp16(d, g);
        }
        cp_commit();
    };

    auto compute = [&](int s) {
        const uint32_t stage = smBase + (uint32_t)s * (STAGE_ELE * 2);
        const uint32_t aH = stage;
        const uint32_t aL = stage + TILE_ELE * 2;
        const uint32_t bH = stage + 2 * TILE_ELE * 2;
        const uint32_t bL = stage + 3 * TILE_ELE * 2;
        #pragma unroll
        for (int kk = 0; kk < 2; kk++) {
            const int k0 = kk * 16;
            uint32_t bh[4][2], bl[4][2];
            #pragma unroll
            for (int j = 0; j < 4; j++) {
                const uint32_t off = (uint32_t)((wn * 32 + j * 8 + gid) * PADK + k0 + tig * 2) * 2;
                bh[j][0] = lds_b32(bH + off); bh[j][1] = lds_b32(bH + off + 16);
                bl[j][0] = lds_b32(bL + off); bl[j][1] = lds_b32(bL + off + 16);
            }
            #pragma unroll
            for (int i = 0; i < 4; i++) {
                const uint32_t offa  = (uint32_t)((wm * 64 + i * 16 + gid) * PADK + k0 + tig * 2) * 2;
                const uint32_t offa8 = offa + 8 * PADK * 2;
                uint32_t ah[4], al[4];
                ah[0] = lds_b32(aH + offa);      ah[1] = lds_b32(aH + offa8);
                ah[2] = lds_b32(aH + offa + 16); ah[3] = lds_b32(aH + offa8 + 16);
                al[0] = lds_b32(aL + offa);      al[1] = lds_b32(aL + offa8);
                al[2] = lds_b32(aL + offa + 16); al[3] = lds_b32(aL + offa8 + 16);
                #pragma unroll
                for (int j = 0; j < 4; j++) {
                    mma_bf16(acc[i][j], ah, bh[j]);
                    mma_bf16(acc[i][j], ah, bl[j]);
                    mma_bf16(acc[i][j], al, bh[j]);
                }
            }
        }
    };

    issue_loads(0, 0);
    for (int ch = 0; ch < nch; ch++) {
        const int s = ch & 1;
        if (ch + 1 < nch) {
            issue_loads(ch + 1, s ^ 1);
            asm volatile("cp.async.wait_group 1;" ::: "memory");
        } else {
            asm volatile("cp.async.wait_group 0;" ::: "memory");
        }
        __syncthreads();
        compute(s);
        __syncthreads();
    }

    const int crow0 = by * 128 + wm * 64;
    const int ccol0 = bx * 128 + wn * 32;
    #pragma unroll
    for (int i = 0; i < 4; i++) {
        #pragma unroll
        for (int j = 0; j < 4; j++) {
            const int r = crow0 + i * 16 + gid;
            const int c = ccol0 + j * 8 + tig * 2;
            const float b0 = bias[c], b1v = bias[c + 1];
            #pragma unroll
            for (int h = 0; h < 2; h++) {
                const int rr = r + h * 8;
                float v0 = acc[i][j][2 * h]     + b0;
                float v1 = acc[i][j][2 * h + 1] + b1v;
                if (EPI == 1) { v0 = fmaxf(v0, 0.0f); v1 = fmaxf(v1, 0.0f); }
                if (EPI == 2) {
                    v0 += R[(size_t)rr * N + c];
                    v1 += R[(size_t)rr * N + c + 1];
                }
                if (OUT == 0) {
                    float2 st = { v0, v1 };
                    *(float2*)&C[(size_t)rr * N + c] = st;
                } else if (OUT == 1) {
                    const bf16 h0 = __float2bfloat16(v0);
                    const bf16 h1 = __float2bfloat16(v1);
                    *(__nv_bfloat162*)&Oh[(size_t)rr * N + c] = __halves2bfloat162(h0, h1);
                    *(__nv_bfloat162*)&Ol[(size_t)rr * N + c] = __halves2bfloat162(
                        __float2bfloat16(v0 - __bfloat162float(h0)),
                        __float2bfloat16(v1 - __bfloat162float(h1)));
                } else {
                    __half* H = (__half*)Oh;
                    *(__half2*)&H[(size_t)rr * N + c] = __floats2half2_rn(v0, v1);
                }
            }
        }
    }
}

// ---------------------------------------------------------------------------
// fp32 -> bf16 hi/lo split
// ---------------------------------------------------------------------------
__global__ __launch_bounds__(256)
void split_kernel(const float* __restrict__ in, bf16* __restrict__ hi,
                  bf16* __restrict__ lo, int n4)
{
    const int i = blockIdx.x * 256 + threadIdx.x;
    if (i >= n4) return;
    const float4 v = ((const float4*)in)[i];
    float a[4] = { v.x, v.y, v.z, v.w };
    bf16 h[4], l[4];
    #pragma unroll
    for (int j = 0; j < 4; j++) {
        h[j] = __float2bfloat16(a[j]);
        l[j] = __float2bfloat16(a[j] - __bfloat162float(h[j]));
    }
    ((__nv_bfloat162*)hi)[2 * i]     = __halves2bfloat162(h[0], h[1]);
    ((__nv_bfloat162*)hi)[2 * i + 1] = __halves2bfloat162(h[2], h[3]);
    ((__nv_bfloat162*)lo)[2 * i]     = __halves2bfloat162(l[0], l[1]);
    ((__nv_bfloat162*)lo)[2 * i + 1] = __halves2bfloat162(l[2], l[3]);
}

// ---------------------------------------------------------------------------
// W[K,N] fp32 -> Wt[N,K] bf16 hi/lo (tiled transpose)
// ---------------------------------------------------------------------------
__global__ __launch_bounds__(256)
void tsplit_kernel(const float* __restrict__ W, bf16* __restrict__ Th,
                   bf16* __restrict__ Tl, int K, int N)
{
    __shared__ float tsm[32][33];
    const int n0 = blockIdx.x * 32, k0 = blockIdx.y * 32;
    const int tx = threadIdx.x, ty = threadIdx.y;
    #pragma unroll
    for (int i = 0; i < 4; i++)
        tsm[ty + 8 * i][tx] = W[(size_t)(k0 + ty + 8 * i) * N + n0 + tx];
    __syncthreads();
    #pragma unroll
    for (int i = 0; i < 4; i++) {
        const int n = n0 + ty + 8 * i;
        const float v = tsm[tx][ty + 8 * i];
        const bf16 h = __float2bfloat16(v);
        const bf16 l = __float2bfloat16(v - __bfloat162float(h));
        Th[(size_t)n * K + k0 + tx] = h;
        Tl[(size_t)n * K + k0 + tx] = l;
    }
}

// ---------------------------------------------------------------------------
// Flash attention v2 (mma.sync f16, causal). Block = 128 q-rows x (b,h).
// 8 warps x 16 rows. K/V tiles of 64 rows, cp.async double-buffered.
// ---------------------------------------------------------------------------
#define FPAD 72
#define FLASH_Q_BYTES  (128 * FPAD * 2)        // 18432
#define FLASH_KV_STAGE (2 * 64 * FPAD * 2)     // 18432
#define FLASH2_SMEM (FLASH_Q_BYTES + 2 * FLASH_KV_STAGE)

__global__ __launch_bounds__(256)
void flash2(const __half* __restrict__ Qf, const __half* __restrict__ Kf,
            const __half* __restrict__ Vf,
            bf16* __restrict__ Ch, bf16* __restrict__ Cl)
{
    const uint32_t smQ  = smem_u32(dynsm);
    const uint32_t smKV = smQ + FLASH_Q_BYTES;

    const int tid  = threadIdx.x;
    const int lane = tid & 31, warp = tid >> 5;
    const int gid  = lane >> 2, tig = lane & 3;
    const int qt = (SEQ / 128 - 1) - blockIdx.x;   // heavy blocks first
    const int bh = blockIdx.y;
    const int b  = bh >> 4, h = bh & 15;

    const int q0 = qt * 128;
    const size_t headOff = (size_t)(b * SEQ) * DM + h * HD;
    const __half* Qg = Qf + headOff + (size_t)q0 * DM;
    const __half* Kg = Kf + headOff;
    const __half* Vg = Vf + headOff;

    const int nkt = 2 * qt + 2;

    // Q tile: 128 rows x 64 f16
    #pragma unroll
    for (int i = 0; i < 4; i++) {
        const int c = tid + i * 256;
        const int r = c >> 3, q = c & 7;
        cp16(smQ + (uint32_t)(r * FPAD + q * 8) * 2, Qg + (size_t)r * DM + q * 8);
    }
    cp_commit();

    auto issue_kv = [&](int ki, int s) {
        const uint32_t base = smKV + (uint32_t)s * FLASH_KV_STAGE;
        const __half* Ksrc = Kg + (size_t)(ki * 64) * DM;
        const __half* Vsrc = Vg + (size_t)(ki * 64) * DM;
        #pragma unroll
        for (int i = 0; i < 4; i++) {
            const int c = tid + i * 256;
            const int hv = c >> 9, w2 = c & 511;
            const int r = w2 >> 3, q = w2 & 7;
            const __half* g = (hv ? Vsrc : Ksrc) + (size_t)r * DM + q * 8;
            cp16(base + (uint32_t)(hv * (64 * FPAD) + r * FPAD + q * 8) * 2, g);
        }
        cp_commit();
    };
    issue_kv(0, 0);
    issue_kv(1, 1);

    asm volatile("cp.async.wait_group 2;" ::: "memory");   // Q ready
    __syncthreads();

    // Q A-fragments (register-resident for the whole block)
    uint32_t qa[4][4];
    {
        const int rbase = warp * 16;
        #pragma unroll
        for (int t = 0; t < 4; t++) {
            const uint32_t off = smQ + (uint32_t)((rbase + gid) * FPAD + t * 16 + tig * 2) * 2;
            qa[t][0] = lds_b32(off);
            qa[t][1] = lds_b32(off + 8 * FPAD * 2);
            qa[t][2] = lds_b32(off + 16);
            qa[t][3] = lds_b32(off + 8 * FPAD * 2 + 16);
        }
    }

    float m0 = -1e30f, m1 = -1e30f, l0 = 0.0f, l1 = 0.0f;
    float O[8][4];
    #pragma unroll
    for (int j = 0; j < 8; j++)
        #pragma unroll
        for (int e = 0; e < 4; e++) O[j][e] = 0.0f;

    const float csc = 0.18033688011112042f;   // log2(e)/sqrt(64)
    const int wrm   = q0 + warp * 16;
    const int rowg0 = wrm + gid;               // row A (row B = +8)

    for (int ki = 0; ki < nkt; ki++) {
        const int s = ki & 1;
        const uint32_t smK = smKV + (uint32_t)s * FLASH_KV_STAGE;
        const uint32_t smV = smK + 64 * FPAD * 2;

        if (ki + 1 < nkt) asm volatile("cp.async.wait_group 1;" ::: "memory");
        else              asm volatile("cp.async.wait_group 0;" ::: "memory");
        __syncthreads();

        // ---- S = Q K^T ----
        float S[8][4];
        #pragma unroll
        for (int j = 0; j < 8; j++)
            #pragma unroll
            for (int e = 0; e < 4; e++) S[j][e] = 0.0f;

        #pragma unroll
        for (int t = 0; t < 4; t++) {
            #pragma unroll
            for (int j = 0; j < 8; j++) {
                const uint32_t boff = smK + (uint32_t)((j * 8 + gid) * FPAD + t * 16 + tig * 2) * 2;
                uint32_t bk[2];
                bk[0] = lds_b32(boff);
                bk[1] = lds_b32(boff + 16);
                mma_f16(S[j], qa[t], bk);
            }
        }

        // ---- scale + causal mask (log2 domain) ----
        const int k0 = ki * 64;
        const bool needMask = (k0 + 63 > wrm);
        #pragma unroll
        for (int j = 0; j < 8; j++) {
            const int colb = k0 + j * 8 + tig * 2;
            #pragma unroll
            for (int e = 0; e < 4; e++) {
                float u = S[j][e] * csc;
                if (needMask) {
                    const int col = colb + (e & 1);
                    const int row = rowg0 + (e >> 1) * 8;
                    if (col > row) u = -1e30f;
                }
                S[j][e] = u;
            }
        }

        // ---- row max across tig quad ----
        float rm0 = S[0][0], rm1 = S[0][2];
        #pragma unroll
        for (int j = 0; j < 8; j++) {
            rm0 = fmaxf(rm0, fmaxf(S[j][0], S[j][1]));
            rm1 = fmaxf(rm1, fmaxf(S[j][2], S[j][3]));
        }
        rm0 = fmaxf(rm0, __shfl_xor_sync(0xffffffffu, rm0, 1));
        rm0 = fmaxf(rm0, __shfl_xor_sync(0xffffffffu, rm0, 2));
        rm1 = fmaxf(rm1, __shfl_xor_sync(0xffffffffu, rm1, 1));
        rm1 = fmaxf(rm1, __shfl_xor_sync(0xffffffffu, rm1, 2));

        const float mn0 = fmaxf(m0, rm0), mn1 = fmaxf(m1, rm1);
        const float a0 = exp2f(m0 - mn0), a1 = exp2f(m1 - mn1);
        m0 = mn0; m1 = mn1;

        // ---- p = exp2(u - m) as packed f16x2 (these ARE the PV A-frags) ----
        uint32_t P[8][2];
        __half2 hs0 = __floats2half2_rn(0.0f, 0.0f);
        __half2 hs1 = hs0;
        #pragma unroll
        for (int j = 0; j < 8; j++) {
            __half2 p0 = h2exp2(__floats2half2_rn(S[j][0] - m0, S[j][1] - m0));
            __half2 p1 = h2exp2(__floats2half2_rn(S[j][2] - m1, S[j][3] - m1));
            P[j][0] = *reinterpret_cast<uint32_t*>(&p0);
            P[j][1] = *reinterpret_cast<uint32_t*>(&p1);
            hs0 = __hadd2(hs0, p0);
            hs1 = __hadd2(hs1, p1);
        }
        float2 f0 = __half22float2(hs0);
        float2 f1 = __half22float2(hs1);
        float rs0 = f0.x + f0.y, rs1 = f1.x + f1.y;
        rs0 += __shfl_xor_sync(0xffffffffu, rs0, 1);
        rs0 += __shfl_xor_sync(0xffffffffu, rs0, 2);
        rs1 += __shfl_xor_sync(0xffffffffu, rs1, 1);
        rs1 += __shfl_xor_sync(0xffffffffu, rs1, 2);
        l0 = l0 * a0 + rs0;
        l1 = l1 * a1 + rs1;

        #pragma unroll
        for (int j = 0; j < 8; j++) {
            O[j][0] *= a0; O[j][1] *= a0;
            O[j][2] *= a1; O[j][3] *= a1;
        }

        // ---- O += P @ V  (V^T B-frags via ldmatrix.x4.trans) ----
        #pragma unroll
        for (int t = 0; t < 4; t++) {
            uint32_t ap[4] = { P[2 * t][0], P[2 * t][1], P[2 * t + 1][0], P[2 * t + 1][1] };
            #pragma unroll
            for (int jp = 0; jp < 4; jp++) {
                const int mat = lane >> 3, r = lane & 7;
                const uint32_t addr = smV +
                    (uint32_t)((t * 16 + (mat & 1) * 8 + r) * FPAD + jp * 16 + (mat >> 1) * 8) * 2;
                uint32_t v0, v1, v2, v3;
                asm volatile(
                    "ldmatrix.sync.aligned.m8n8.x4.trans.shared.b16 {%0,%1,%2,%3}, [%4];"
                    : "=r"(v0), "=r"(v1), "=r"(v2), "=r"(v3) : "r"(addr));
                uint32_t bv0[2] = { v0, v1 }, bv1[2] = { v2, v3 };
                mma_f16(O[2 * jp],     ap, bv0);
                mma_f16(O[2 * jp + 1], ap, bv1);
            }
        }

        __syncthreads();
        if (ki + 2 < nkt) issue_kv(ki + 2, s);
    }

    // ---- epilogue: ctx = O / l, bf16 hi/lo ----
    const float inv0 = 1.0f / l0, inv1 = 1.0f / l1;
    #pragma unroll
    for (int j = 0; j < 8; j++) {
        const int col = j * 8 + tig * 2;
        #pragma unroll
        for (int e = 0; e < 2; e++) {
            const int rowg = rowg0 + e * 8;
            const float inv = e ? inv1 : inv0;
            const float v0 = O[j][2 * e]     * inv;
            const float v1 = O[j][2 * e + 1] * inv;
            const size_t idx = (size_t)(b * SEQ + rowg) * DM + h * HD + col;
            const bf16 h0 = __float2bfloat16(v0);
            const bf16 h1 = __float2bfloat16(v1);
            *(__nv_bfloat162*)&Ch[idx] = __halves2bfloat162(h0, h1);
            *(__nv_bfloat162*)&Cl[idx] = __halves2bfloat162(
                __float2bfloat16(v0 - __bfloat162float(h0)),
                __float2bfloat16(v1 - __bfloat162float(h1)));
        }
    }
}

// ---------------------------------------------------------------------------
// LayerNorm over last dim (1024). Optional fused bf16 hi/lo output.
// ---------------------------------------------------------------------------
template<bool BFOUT>
__global__ __launch_bounds__(256)
void ln_kernel(const float* __restrict__ in, const float* __restrict__ g,
               const float* __restrict__ be, float* __restrict__ out,
               bf16* __restrict__ oh, bf16* __restrict__ ol)
{
    const int row = blockIdx.x;
    const float4 v = ((const float4*)(in + (size_t)row * DM))[threadIdx.x];

    float s  = v.x + v.y + v.z + v.w;
    float ss = fmaf(v.x, v.x, fmaf(v.y, v.y, fmaf(v.z, v.z, v.w * v.w)));

    #pragma unroll
    for (int off = 16; off; off >>= 1) {
        s  += __shfl_xor_sync(0xffffffffu, s,  off);
        ss += __shfl_xor_sync(0xffffffffu, ss, off);
    }

    __shared__ float sred[8], ssred[8];
    const int w = threadIdx.x >> 5, lane = threadIdx.x & 31;
    if (lane == 0) { sred[w] = s; ssred[w] = ss; }
    __syncthreads();
    if (w == 0) {
        float a  = (lane < 8) ? sred[lane]  : 0.0f;
        float bb = (lane < 8) ? ssred[lane] : 0.0f;
        #pragma unroll
        for (int off = 4; off; off >>= 1) {
            a  += __shfl_xor_sync(0xffffffffu, a,  off);
            bb += __shfl_xor_sync(0xffffffffu, bb, off);
        }
        if (lane == 0) { sred[0] = a; ssred[0] = bb; }
    }
    __syncthreads();

    const float mean = sred[0] * (1.0f / DM);
    const float var  = ssred[0] * (1.0f / DM) - mean * mean;
    const float inv  = rsqrtf(var + 1e-6f);

    const float4 gv = ((const float4*)g)[threadIdx.x];
    const float4 bv = ((const float4*)be)[threadIdx.x];
    float o[4];
    o[0] = (v.x - mean) * inv * gv.x + bv.x;
    o[1] = (v.y - mean) * inv * gv.y + bv.y;
    o[2] = (v.z - mean) * inv * gv.z + bv.z;
    o[3] = (v.w - mean) * inv * gv.w + bv.w;
    float4 of = { o[0], o[1], o[2], o[3] };
    ((float4*)(out + (size_t)row * DM))[threadIdx.x] = of;

    if (BFOUT) {
        const size_t base2 = (size_t)row * (DM / 2) + threadIdx.x * 2;
        bf16 h[4], l[4];
        #pragma unroll
        for (int j = 0; j < 4; j++) {
            h[j] = __float2bfloat16(o[j]);
            l[j] = __float2bfloat16(o[j] - __bfloat162float(h[j]));
        }
        ((__nv_bfloat162*)oh)[base2]     = __halves2bfloat162(h[0], h[1]);
        ((__nv_bfloat162*)oh)[base2 + 1] = __halves2bfloat162(h[2], h[3]);
        ((__nv_bfloat162*)ol)[base2]     = __halves2bfloat162(l[0], l[1]);
        ((__nv_bfloat162*)ol)[base2 + 1] = __halves2bfloat162(l[2], l[3]);
    }
}

// ---------------------------------------------------------------------------
// Launch
// ---------------------------------------------------------------------------
extern "C" void kernel_launch(void* const* d_in, const int* in_sizes, int n_in,
                              void* d_out, int out_size)
{
    const float* x   = (const float*)d_in[0];
    const float* wq  = (const float*)d_in[2];
    const float* bq  = (const float*)d_in[3];
    const float* wk  = (const float*)d_in[4];
    const float* bk  = (const float*)d_in[5];
    const float* wv  = (const float*)d_in[6];
    const float* bv  = (const float*)d_in[7];
    const float* wo  = (const float*)d_in[8];
    const float* bo  = (const float*)d_in[9];
    const float* g1  = (const float*)d_in[10];
    const float* be1 = (const float*)d_in[11];
    const float* w1  = (const float*)d_in[12];
    const float* b1  = (const float*)d_in[13];
    const float* w2  = (const float*)d_in[14];
    const float* b2  = (const float*)d_in[15];
    const float* g2  = (const float*)d_in[16];
    const float* be2 = (const float*)d_in[17];
    float* out = (float*)d_out;

    float *res1, *out1, *res2;
    cudaGetSymbolAddress((void**)&res1, g_res1);
    cudaGetSymbolAddress((void**)&out1, g_out1);
    cudaGetSymbolAddress((void**)&res2, g_res2);

    __half *qf, *kf, *vf;
    cudaGetSymbolAddress((void**)&qf, g_qf);
    cudaGetSymbolAddress((void**)&kf, g_kf);
    cudaGetSymbolAddress((void**)&vf, g_vf);

    bf16 *xh, *xl, *ch, *cl, *o1h, *o1l, *hh, *hl;
    bf16 *wqh, *wql, *wkh, *wkl, *wvh, *wvl, *woh, *wol, *w1h, *w1l, *w2h, *w2l;
    cudaGetSymbolAddress((void**)&xh,  g_xh);   cudaGetSymbolAddress((void**)&xl,  g_xl);
    cudaGetSymbolAddress((void**)&ch,  g_ch);   cudaGetSymbolAddress((void**)&cl,  g_cl);
    cudaGetSymbolAddress((void**)&o1h, g_o1h);  cudaGetSymbolAddress((void**)&o1l, g_o1l);
    cudaGetSymbolAddress((void**)&hh,  g_hh);   cudaGetSymbolAddress((void**)&hl,  g_hl);
    cudaGetSymbolAddress((void**)&wqh, g_wqh);  cudaGetSymbolAddress((void**)&wql, g_wql);
    cudaGetSymbolAddress((void**)&wkh, g_wkh);  cudaGetSymbolAddress((void**)&wkl, g_wkl);
    cudaGetSymbolAddress((void**)&wvh, g_wvh);  cudaGetSymbolAddress((void**)&wvl, g_wvl);
    cudaGetSymbolAddress((void**)&woh, g_woh);  cudaGetSymbolAddress((void**)&wol, g_wol);
    cudaGetSymbolAddress((void**)&w1h, g_w1h);  cudaGetSymbolAddress((void**)&w1l, g_w1l);
    cudaGetSymbolAddress((void**)&w2h, g_w2h);  cudaGetSymbolAddress((void**)&w2l, g_w2l);

    cudaFuncSetAttribute(flash2, cudaFuncAttributeMaxDynamicSharedMemorySize, FLASH2_SMEM);
    cudaFuncSetAttribute((const void*)gemm_mma<0, 2>, cudaFuncAttributeMaxDynamicSharedMemorySize, GEMM_SMEM_BYTES);
    cudaFuncSetAttribute((const void*)gemm_mma<1, 1>, cudaFuncAttributeMaxDynamicSharedMemorySize, GEMM_SMEM_BYTES);
    cudaFuncSetAttribute((const void*)gemm_mma<2, 0>, cudaFuncAttributeMaxDynamicSharedMemorySize, GEMM_SMEM_BYTES);

    const dim3 blk(256);
    const dim3 tblk(32, 8);

    // Operand prep
    tsplit_kernel<<<dim3(DM / 32,  DM / 32),  tblk>>>(wq, wqh, wql, DM, DM);
    tsplit_kernel<<<dim3(DM / 32,  DM / 32),  tblk>>>(wk, wkh, wkl, DM, DM);
    tsplit_kernel<<<dim3(DM / 32,  DM / 32),  tblk>>>(wv, wvh, wvl, DM, DM);
    tsplit_kernel<<<dim3(DM / 32,  DM / 32),  tblk>>>(wo, woh, wol, DM, DM);
    tsplit_kernel<<<dim3(DFF_ / 32, DM / 32), tblk>>>(w1, w1h, w1l, DM, DFF_);
    tsplit_kernel<<<dim3(DM / 32, DFF_ / 32), tblk>>>(w2, w2h, w2l, DFF_, DM);
    split_kernel<<<(NTOK * DM / 4 + 255) / 256, blk>>>(x, xh, xl, NTOK * DM / 4);

    const dim3 gD(DM / 128,   NTOK / 128);
    const dim3 gF(DFF_ / 128, NTOK / 128);

    // Q/K/V projections (f16 out for flash)
    gemm_mma<0, 2><<<gD, blk, GEMM_SMEM_BYTES>>>(xh, xl, wqh, wql, bq, nullptr, nullptr, (bf16*)qf, nullptr, NTOK, DM, DM);
    gemm_mma<0, 2><<<gD, blk, GEMM_SMEM_BYTES>>>(xh, xl, wkh, wkl, bk, nullptr, nullptr, (bf16*)kf, nullptr, NTOK, DM, DM);
    gemm_mma<0, 2><<<gD, blk, GEMM_SMEM_BYTES>>>(xh, xl, wvh, wvl, bv, nullptr, nullptr, (bf16*)vf, nullptr, NTOK, DM, DM);

    // Causal flash attention -> ctx (bf16 hi/lo)
    flash2<<<dim3(SEQ / 128, 2 * NH), blk, FLASH2_SMEM>>>(qf, kf, vf, ch, cl);

    // res1 = x + ctx @ wo + bo ; out1 = LN(res1) (+ hi/lo)
    gemm_mma<2, 0><<<gD, blk, GEMM_SMEM_BYTES>>>(ch, cl, woh, wol, bo, x, res1, nullptr, nullptr, NTOK, DM, DM);
    ln_kernel<true><<<NTOK, blk>>>(res1, g1, be1, out1, o1h, o1l);

    // hid = relu(out1 @ w1 + b1)  (bf16 hi/lo only)
    gemm_mma<1, 1><<<gF, blk, GEMM_SMEM_BYTES>>>(o1h, o1l, w1h, w1l, b1, nullptr, nullptr, hh, hl, NTOK, DFF_, DM);

    // res2 = out1 + hid @ w2 + b2 ; out = LN(res2)
    gemm_mma<2, 0><<<gD, blk, GEMM_SMEM_BYTES>>>(hh, hl, w2h, w2l, b2, out1, res2, nullptr, nullptr, NTOK, DM, DFF_);
    ln_kernel<false><<<NTOK, blk>>>(res2, g2, be2, out, nullptr, nullptr);
}

// round 15
// speedup vs baseline: 1.0037x; 1.0037x over previous
#include <cuda_runtime.h>
#include <cuda_bf16.h>
#include <cuda_fp16.h>
#include <math.h>
#include <stdint.h>

// ---------------------------------------------------------------------------
// TransformerBlock on GB300 (sm_103a via compute_103 PTX).
// GEMMs: mma.sync m16n8k16 bf16 hi/lo-split (3-product), fp32 accumulate.
// Attention: mma.sync f16 flash (f16 Q/K/V, log2-domain softmax, f16x2 exp,
//            P kept in registers as PV A-fragments, V^T via ldmatrix.trans).
// ---------------------------------------------------------------------------

#define NTOK   4096   // B*S
#define DM     1024
#define DFF_   4096
#define SEQ    2048
#define NH     16
#define HD     64

typedef __nv_bfloat16 bf16;

extern __shared__ char dynsm[];   // single dynamic-smem symbol for all kernels

// ------------------------------- scratch ----------------------------------
__device__ __align__(256) float g_res1[NTOK * DM];
__device__ __align__(256) float g_out1[NTOK * DM];
__device__ __align__(256) float g_res2[NTOK * DM];

__device__ __align__(256) __half g_qf[NTOK * DM];
__device__ __align__(256) __half g_kf[NTOK * DM];
__device__ __align__(256) __half g_vf[NTOK * DM];

__device__ __align__(256) bf16 g_xh [NTOK * DM],   g_xl [NTOK * DM];
__device__ __align__(256) bf16 g_ch [NTOK * DM],   g_cl [NTOK * DM];   // ctx
__device__ __align__(256) bf16 g_o1h[NTOK * DM],   g_o1l[NTOK * DM];   // out1
__device__ __align__(256) bf16 g_hh [NTOK * DFF_], g_hl [NTOK * DFF_]; // hid
__device__ __align__(256) bf16 g_wqh[DM * DM],   g_wql[DM * DM];
__device__ __align__(256) bf16 g_wkh[DM * DM],   g_wkl[DM * DM];
__device__ __align__(256) bf16 g_wvh[DM * DM],   g_wvl[DM * DM];
__device__ __align__(256) bf16 g_woh[DM * DM],   g_wol[DM * DM];
__device__ __align__(256) bf16 g_w1h[DFF_ * DM], g_w1l[DFF_ * DM];
__device__ __align__(256) bf16 g_w2h[DM * DFF_], g_w2l[DM * DFF_];

// --------------------------- device helpers --------------------------------
__device__ __forceinline__ uint32_t smem_u32(const void* p) {
    uint32_t a;
    asm("{ .reg .u64 t; cvta.to.shared.u64 t, %1; cvt.u32.u64 %0, t; }" : "=r"(a) : "l"(p));
    return a;
}
__device__ __forceinline__ uint32_t lds_b32(uint32_t addr) {
    uint32_t v;
    asm volatile("ld.shared.b32 %0, [%1];" : "=r"(v) : "r"(addr));
    return v;
}
__device__ __forceinline__ void cp16(uint32_t dst, const void* src) {
    asm volatile("cp.async.cg.shared.global [%0], [%1], 16;" :: "r"(dst), "l"(src) : "memory");
}
__device__ __forceinline__ void cp_commit() {
    asm volatile("cp.async.commit_group;" ::: "memory");
}
__device__ __forceinline__ void mma_bf16(float* d, const uint32_t* a, const uint32_t* b) {
    asm volatile(
        "mma.sync.aligned.m16n8k16.row.col.f32.bf16.bf16.f32 "
        "{%0,%1,%2,%3}, {%4,%5,%6,%7}, {%8,%9}, {%0,%1,%2,%3};"
        : "+f"(d[0]), "+f"(d[1]), "+f"(d[2]), "+f"(d[3])
        : "r"(a[0]), "r"(a[1]), "r"(a[2]), "r"(a[3]), "r"(b[0]), "r"(b[1]));
}
__device__ __forceinline__ void mma_f16(float* d, const uint32_t* a, const uint32_t* b) {
    asm volatile(
        "mma.sync.aligned.m16n8k16.row.col.f32.f16.f16.f32 "
        "{%0,%1,%2,%3}, {%4,%5,%6,%7}, {%8,%9}, {%0,%1,%2,%3};"
        : "+f"(d[0]), "+f"(d[1]), "+f"(d[2]), "+f"(d[3])
        : "r"(a[0]), "r"(a[1]), "r"(a[2]), "r"(a[3]), "r"(b[0]), "r"(b[1]));
}

// ---------------------------------------------------------------------------
// GEMM: C[M,N] = (Ah+Al)[M,K] @ (Bh+Bl)[N,K]^T + bias (+relu/+residual)
// 128x128 tile, BK=32, 256 threads (2x4 warps), warp tile 64x32.
// EPI: 0=bias, 1=bias+relu, 2=bias+residual.
// OUT: 0=f32 to C, 1=bf16 hi/lo to Oh/Ol, 2=f16 to (half*)Oh.
// ---------------------------------------------------------------------------
#define PADK 40
#define TILE_ELE (128 * PADK)
#define STAGE_ELE (4 * TILE_ELE)
#define GEMM_SMEM_BYTES (2 * STAGE_ELE * 2)   // 81920 B

template<int EPI, int OUT>
__global__ __launch_bounds__(256, 2)
void gemm_mma(const bf16* __restrict__ Ah, const bf16* __restrict__ Al,
              const bf16* __restrict__ Bh, const bf16* __restrict__ Bl,
              const float* __restrict__ bias, const float* __restrict__ R,
              float* __restrict__ C, bf16* __restrict__ Oh, bf16* __restrict__ Ol,
              int M, int N, int K)
{
    const uint32_t smBase = smem_u32(dynsm);

    const int tid  = threadIdx.x;
    const int lane = tid & 31, warp = tid >> 5;
    const int wm = warp >> 2, wn = warp & 3;
    const int gid = lane >> 2, tig = lane & 3;
    const int bx = blockIdx.x, by = blockIdx.y;

    const bf16* src[4] = { Ah + (size_t)by * 128 * K, Al + (size_t)by * 128 * K,
                           Bh + (size_t)bx * 128 * K, Bl + (size_t)bx * 128 * K };

    float acc[4][4][4];
    #pragma unroll
    for (int i = 0; i < 4; i++)
        #pragma unroll
        for (int j = 0; j < 4; j++)
            #pragma unroll
            for (int h = 0; h < 4; h++) acc[i][j][h] = 0.0f;

    const int nch = K >> 5;

    auto issue_loads = [&](int ch, int s) {
        const int kof = ch << 5;
        const uint32_t stage = smBase + (uint32_t)s * (STAGE_ELE * 2);
        #pragma unroll
        for (int i = 0; i < 8; i++) {
            const int c = tid + (i << 8);
            const int tile = c >> 9, w = c & 511, row = w >> 2, q = w & 3;
            const bf16* g = src[tile] + (size_t)row * K + kof + q * 8;
            const uint32_t d = stage + (uint32_t)(tile * TILE_ELE + row * PADK + q * 8) * 2;
            cp16(d, g);
        }
        cp_commit();
    };

    auto compute = [&](int s) {
        const uint32_t stage = smBase + (uint32_t)s * (STAGE_ELE * 2);
        const uint32_t aH = stage;
        const uint32_t aL = stage + TILE_ELE * 2;
        const uint32_t bH = stage + 2 * TILE_ELE * 2;
        const uint32_t bL = stage + 3 * TILE_ELE * 2;
        #pragma unroll
        for (int kk = 0; kk < 2; kk++) {
            const int k0 = kk * 16;
            uint32_t bh[4][2], bl[4][2];
            #pragma unroll
            for (int j = 0; j < 4; j++) {
                const uint32_t off = (uint32_t)((wn * 32 + j * 8 + gid) * PADK + k0 + tig * 2) * 2;
                bh[j][0] = lds_b32(bH + off); bh[j][1] = lds_b32(bH + off + 16);
                bl[j][0] = lds_b32(bL + off); bl[j][1] = lds_b32(bL + off + 16);
            }
            #pragma unroll
            for (int i = 0; i < 4; i++) {
                const uint32_t offa  = (uint32_t)((wm * 64 + i * 16 + gid) * PADK + k0 + tig * 2) * 2;
                const uint32_t offa8 = offa + 8 * PADK * 2;
                uint32_t ah[4], al[4];
                ah[0] = lds_b32(aH + offa);      ah[1] = lds_b32(aH + offa8);
                ah[2] = lds_b32(aH + offa + 16); ah[3] = lds_b32(aH + offa8 + 16);
                al[0] = lds_b32(aL + offa);      al[1] = lds_b32(aL + offa8);
                al[2] = lds_b32(aL + offa + 16); al[3] = lds_b32(aL + offa8 + 16);
                #pragma unroll
                for (int j = 0; j < 4; j++) {
                    mma_bf16(acc[i][j], ah, bh[j]);
                    mma_bf16(acc[i][j], ah, bl[j]);
                    mma_bf16(acc[i][j], al, bh[j]);
                }
            }
        }
    };

    issue_loads(0, 0);
    for (int ch = 0; ch < nch; ch++) {
        const int s = ch & 1;
        if (ch + 1 < nch) {
            issue_loads(ch + 1, s ^ 1);
            asm volatile("cp.async.wait_group 1;" ::: "memory");
        } else {
            asm volatile("cp.async.wait_group 0;" ::: "memory");
        }
        __syncthreads();
        compute(s);
        __syncthreads();
    }

    const int crow0 = by * 128 + wm * 64;
    const int ccol0 = bx * 128 + wn * 32;
    #pragma unroll
    for (int i = 0; i < 4; i++) {
        #pragma unroll
        for (int j = 0; j < 4; j++) {
            const int r = crow0 + i * 16 + gid;
            const int c = ccol0 + j * 8 + tig * 2;
            const float b0 = bias[c], b1v = bias[c + 1];
            #pragma unroll
            for (int h = 0; h < 2; h++) {
                const int rr = r + h * 8;
                float v0 = acc[i][j][2 * h]     + b0;
                float v1 = acc[i][j][2 * h + 1] + b1v;
                if (EPI == 1) { v0 = fmaxf(v0, 0.0f); v1 = fmaxf(v1, 0.0f); }
                if (EPI == 2) {
                    v0 += R[(size_t)rr * N + c];
                    v1 += R[(size_t)rr * N + c + 1];
                }
                if (OUT == 0) {
                    float2 st = { v0, v1 };
                    *(float2*)&C[(size_t)rr * N + c] = st;
                } else if (OUT == 1) {
                    const bf16 h0 = __float2bfloat16(v0);
                    const bf16 h1 = __float2bfloat16(v1);
                    *(__nv_bfloat162*)&Oh[(size_t)rr * N + c] = __halves2bfloat162(h0, h1);
                    *(__nv_bfloat162*)&Ol[(size_t)rr * N + c] = __halves2bfloat162(
                        __float2bfloat16(v0 - __bfloat162float(h0)),
                        __float2bfloat16(v1 - __bfloat162float(h1)));
                } else {
                    __half* H = (__half*)Oh;
                    *(__half2*)&H[(size_t)rr * N + c] = __floats2half2_rn(v0, v1);
                }
            }
        }
    }
}

// ---------------------------------------------------------------------------
// fp32 -> bf16 hi/lo split
// ---------------------------------------------------------------------------
__global__ __launch_bounds__(256)
void split_kernel(const float* __restrict__ in, bf16* __restrict__ hi,
                  bf16* __restrict__ lo, int n4)
{
    const int i = blockIdx.x * 256 + threadIdx.x;
    if (i >= n4) return;
    const float4 v = ((const float4*)in)[i];
    float a[4] = { v.x, v.y, v.z, v.w };
    bf16 h[4], l[4];
    #pragma unroll
    for (int j = 0; j < 4; j++) {
        h[j] = __float2bfloat16(a[j]);
        l[j] = __float2bfloat16(a[j] - __bfloat162float(h[j]));
    }
    ((__nv_bfloat162*)hi)[2 * i]     = __halves2bfloat162(h[0], h[1]);
    ((__nv_bfloat162*)hi)[2 * i + 1] = __halves2bfloat162(h[2], h[3]);
    ((__nv_bfloat162*)lo)[2 * i]     = __halves2bfloat162(l[0], l[1]);
    ((__nv_bfloat162*)lo)[2 * i + 1] = __halves2bfloat162(l[2], l[3]);
}

// ---------------------------------------------------------------------------
// W[K,N] fp32 -> Wt[N,K] bf16 hi/lo (tiled transpose)
// ---------------------------------------------------------------------------
__global__ __launch_bounds__(256)
void tsplit_kernel(const float* __restrict__ W, bf16* __restrict__ Th,
                   bf16* __restrict__ Tl, int K, int N)
{
    __shared__ float tsm[32][33];
    const int n0 = blockIdx.x * 32, k0 = blockIdx.y * 32;
    const int tx = threadIdx.x, ty = threadIdx.y;
    #pragma unroll
    for (int i = 0; i < 4; i++)
        tsm[ty + 8 * i][tx] = W[(size_t)(k0 + ty + 8 * i) * N + n0 + tx];
    __syncthreads();
    #pragma unroll
    for (int i = 0; i < 4; i++) {
        const int n = n0 + ty + 8 * i;
        const float v = tsm[tx][ty + 8 * i];
        const bf16 h = __float2bfloat16(v);
        const bf16 l = __float2bfloat16(v - __bfloat162float(h));
        Th[(size_t)n * K + k0 + tx] = h;
        Tl[(size_t)n * K + k0 + tx] = l;
    }
}

// ---------------------------------------------------------------------------
// Flash attention v2 (mma.sync f16, causal). Block = 128 q-rows x (b,h).
// 8 warps x 16 rows. K/V tiles of 64 rows, cp.async double-buffered.
// ---------------------------------------------------------------------------
#define FPAD 72
#define FLASH_Q_BYTES  (128 * FPAD * 2)        // 18432
#define FLASH_KV_STAGE (2 * 64 * FPAD * 2)     // 18432
#define FLASH2_SMEM (FLASH_Q_BYTES + 2 * FLASH_KV_STAGE)

__global__ __launch_bounds__(256)
void flash2(const __half* __restrict__ Qf, const __half* __restrict__ Kf,
            const __half* __restrict__ Vf,
            bf16* __restrict__ Ch, bf16* __restrict__ Cl)
{
    const uint32_t smQ  = smem_u32(dynsm);
    const uint32_t smKV = smQ + FLASH_Q_BYTES;

    const int tid  = threadIdx.x;
    const int lane = tid & 31, warp = tid >> 5;
    const int gid  = lane >> 2, tig = lane & 3;
    const int qt = (SEQ / 128 - 1) - blockIdx.x;   // heavy blocks first
    const int bh = blockIdx.y;
    const int b  = bh >> 4, h = bh & 15;

    const int q0 = qt * 128;
    const size_t headOff = (size_t)(b * SEQ) * DM + h * HD;
    const __half* Qg = Qf + headOff + (size_t)q0 * DM;
    const __half* Kg = Kf + headOff;
    const __half* Vg = Vf + headOff;

    const int nkt = 2 * qt + 2;

    // Q tile: 128 rows x 64 f16
    #pragma unroll
    for (int i = 0; i < 4; i++) {
        const int c = tid + i * 256;
        const int r = c >> 3, q = c & 7;
        cp16(smQ + (uint32_t)(r * FPAD + q * 8) * 2, Qg + (size_t)r * DM + q * 8);
    }
    cp_commit();

    auto issue_kv = [&](int ki, int s) {
        const uint32_t base = smKV + (uint32_t)s * FLASH_KV_STAGE;
        const __half* Ksrc = Kg + (size_t)(ki * 64) * DM;
        const __half* Vsrc = Vg + (size_t)(ki * 64) * DM;
        #pragma unroll
        for (int i = 0; i < 4; i++) {
            const int c = tid + i * 256;
            const int hv = c >> 9, w2 = c & 511;
            const int r = w2 >> 3, q = w2 & 7;
            const __half* g = (hv ? Vsrc : Ksrc) + (size_t)r * DM + q * 8;
            cp16(base + (uint32_t)(hv * (64 * FPAD) + r * FPAD + q * 8) * 2, g);
        }
        cp_commit();
    };
    issue_kv(0, 0);
    issue_kv(1, 1);

    asm volatile("cp.async.wait_group 2;" ::: "memory");   // Q ready
    __syncthreads();

    // Q A-fragments (register-resident for the whole block)
    uint32_t qa[4][4];
    {
        const int rbase = warp * 16;
        #pragma unroll
        for (int t = 0; t < 4; t++) {
            const uint32_t off = smQ + (uint32_t)((rbase + gid) * FPAD + t * 16 + tig * 2) * 2;
            qa[t][0] = lds_b32(off);
            qa[t][1] = lds_b32(off + 8 * FPAD * 2);
            qa[t][2] = lds_b32(off + 16);
            qa[t][3] = lds_b32(off + 8 * FPAD * 2 + 16);
        }
    }

    float m0 = -1e30f, m1 = -1e30f, l0 = 0.0f, l1 = 0.0f;
    float O[8][4];
    #pragma unroll
    for (int j = 0; j < 8; j++)
        #pragma unroll
        for (int e = 0; e < 4; e++) O[j][e] = 0.0f;

    const float csc = 0.18033688011112042f;   // log2(e)/sqrt(64)
    const int wrm   = q0 + warp * 16;
    const int rowg0 = wrm + gid;               // row A (row B = +8)

    for (int ki = 0; ki < nkt; ki++) {
        const int s = ki & 1;
        const uint32_t smK = smKV + (uint32_t)s * FLASH_KV_STAGE;
        const uint32_t smV = smK + 64 * FPAD * 2;

        if (ki + 1 < nkt) asm volatile("cp.async.wait_group 1;" ::: "memory");
        else              asm volatile("cp.async.wait_group 0;" ::: "memory");
        __syncthreads();

        // ---- S = Q K^T ----
        float S[8][4];
        #pragma unroll
        for (int j = 0; j < 8; j++)
            #pragma unroll
            for (int e = 0; e < 4; e++) S[j][e] = 0.0f;

        #pragma unroll
        for (int t = 0; t < 4; t++) {
            #pragma unroll
            for (int j = 0; j < 8; j++) {
                const uint32_t boff = smK + (uint32_t)((j * 8 + gid) * FPAD + t * 16 + tig * 2) * 2;
                uint32_t bk[2];
                bk[0] = lds_b32(boff);
                bk[1] = lds_b32(boff + 16);
                mma_f16(S[j], qa[t], bk);
            }
        }

        // ---- scale + causal mask (log2 domain) ----
        const int k0 = ki * 64;
        const bool needMask = (k0 + 63 > wrm);
        #pragma unroll
        for (int j = 0; j < 8; j++) {
            const int colb = k0 + j * 8 + tig * 2;
            #pragma unroll
            for (int e = 0; e < 4; e++) {
                float u = S[j][e] * csc;
                if (needMask) {
                    const int col = colb + (e & 1);
                    const int row = rowg0 + (e >> 1) * 8;
                    if (col > row) u = -1e30f;
                }
                S[j][e] = u;
            }
        }

        // ---- row max across tig quad ----
        float rm0 = S[0][0], rm1 = S[0][2];
        #pragma unroll
        for (int j = 0; j < 8; j++) {
            rm0 = fmaxf(rm0, fmaxf(S[j][0], S[j][1]));
            rm1 = fmaxf(rm1, fmaxf(S[j][2], S[j][3]));
        }
        rm0 = fmaxf(rm0, __shfl_xor_sync(0xffffffffu, rm0, 1));
        rm0 = fmaxf(rm0, __shfl_xor_sync(0xffffffffu, rm0, 2));
        rm1 = fmaxf(rm1, __shfl_xor_sync(0xffffffffu, rm1, 1));
        rm1 = fmaxf(rm1, __shfl_xor_sync(0xffffffffu, rm1, 2));

        const float mn0 = fmaxf(m0, rm0), mn1 = fmaxf(m1, rm1);
        const float a0 = exp2f(m0 - mn0), a1 = exp2f(m1 - mn1);
        m0 = mn0; m1 = mn1;

        // ---- p = exp2(u - m) as packed f16x2 (these ARE the PV A-frags) ----
        uint32_t P[8][2];
        __half2 hs0 = __floats2half2_rn(0.0f, 0.0f);
        __half2 hs1 = hs0;
        #pragma unroll
        for (int j = 0; j < 8; j++) {
            __half2 p0 = h2exp2(__floats2half2_rn(S[j][0] - m0, S[j][1] - m0));
            __half2 p1 = h2exp2(__floats2half2_rn(S[j][2] - m1, S[j][3] - m1));
            P[j][0] = *reinterpret_cast<uint32_t*>(&p0);
            P[j][1] = *reinterpret_cast<uint32_t*>(&p1);
            hs0 = __hadd2(hs0, p0);
            hs1 = __hadd2(hs1, p1);
        }
        float2 f0 = __half22float2(hs0);
        float2 f1 = __half22float2(hs1);
        float rs0 = f0.x + f0.y, rs1 = f1.x + f1.y;
        rs0 += __shfl_xor_sync(0xffffffffu, rs0, 1);
        rs0 += __shfl_xor_sync(0xffffffffu, rs0, 2);
        rs1 += __shfl_xor_sync(0xffffffffu, rs1, 1);
        rs1 += __shfl_xor_sync(0xffffffffu, rs1, 2);
        l0 = l0 * a0 + rs0;
        l1 = l1 * a1 + rs1;

        #pragma unroll
        for (int j = 0; j < 8; j++) {
            O[j][0] *= a0; O[j][1] *= a0;
            O[j][2] *= a1; O[j][3] *= a1;
        }

        // ---- O += P @ V  (V^T B-frags via ldmatrix.x4.trans) ----
        #pragma unroll
        for (int t = 0; t < 4; t++) {
            uint32_t ap[4] = { P[2 * t][0], P[2 * t][1], P[2 * t + 1][0], P[2 * t + 1][1] };
            #pragma unroll
            for (int jp = 0; jp < 4; jp++) {
                const int mat = lane >> 3, r = lane & 7;
                const uint32_t addr = smV +
                    (uint32_t)((t * 16 + (mat & 1) * 8 + r) * FPAD + jp * 16 + (mat >> 1) * 8) * 2;
                uint32_t v0, v1, v2, v3;
                asm volatile(
                    "ldmatrix.sync.aligned.m8n8.x4.trans.shared.b16 {%0,%1,%2,%3}, [%4];"
                    : "=r"(v0), "=r"(v1), "=r"(v2), "=r"(v3) : "r"(addr));
                uint32_t bv0[2] = { v0, v1 }, bv1[2] = { v2, v3 };
                mma_f16(O[2 * jp],     ap, bv0);
                mma_f16(O[2 * jp + 1], ap, bv1);
            }
        }

        __syncthreads();
        if (ki + 2 < nkt) issue_kv(ki + 2, s);
    }

    // ---- epilogue: ctx = O / l, bf16 hi/lo ----
    const float inv0 = 1.0f / l0, inv1 = 1.0f / l1;
    #pragma unroll
    for (int j = 0; j < 8; j++) {
        const int col = j * 8 + tig * 2;
        #pragma unroll
        for (int e = 0; e < 2; e++) {
            const int rowg = rowg0 + e * 8;
            const float inv = e ? inv1 : inv0;
            const float v0 = O[j][2 * e]     * inv;
            const float v1 = O[j][2 * e + 1] * inv;
            const size_t idx = (size_t)(b * SEQ + rowg) * DM + h * HD + col;
            const bf16 h0 = __float2bfloat16(v0);
            const bf16 h1 = __float2bfloat16(v1);
            *(__nv_bfloat162*)&Ch[idx] = __halves2bfloat162(h0, h1);
            *(__nv_bfloat162*)&Cl[idx] = __halves2bfloat162(
                __float2bfloat16(v0 - __bfloat162float(h0)),
                __float2bfloat16(v1 - __bfloat162float(h1)));
        }
    }
}

// ---------------------------------------------------------------------------
// LayerNorm over last dim (1024). Optional fused bf16 hi/lo output.
// ---------------------------------------------------------------------------
template<bool BFOUT>
__global__ __launch_bounds__(256)
void ln_kernel(const float* __restrict__ in, const float* __restrict__ g,
               const float* __restrict__ be, float* __restrict__ out,
               bf16* __restrict__ oh, bf16* __restrict__ ol)
{
    const int row = blockIdx.x;
    const float4 v = ((const float4*)(in + (size_t)row * DM))[threadIdx.x];

    float s  = v.x + v.y + v.z + v.w;
    float ss = fmaf(v.x, v.x, fmaf(v.y, v.y, fmaf(v.z, v.z, v.w * v.w)));

    #pragma unroll
    for (int off = 16; off; off >>= 1) {
        s  += __shfl_xor_sync(0xffffffffu, s,  off);
        ss += __shfl_xor_sync(0xffffffffu, ss, off);
    }

    __shared__ float sred[8], ssred[8];
    const int w = threadIdx.x >> 5, lane = threadIdx.x & 31;
    if (lane == 0) { sred[w] = s; ssred[w] = ss; }
    __syncthreads();
    if (w == 0) {
        float a  = (lane < 8) ? sred[lane]  : 0.0f;
        float bb = (lane < 8) ? ssred[lane] : 0.0f;
        #pragma unroll
        for (int off = 4; off; off >>= 1) {
            a  += __shfl_xor_sync(0xffffffffu, a,  off);
            bb += __shfl_xor_sync(0xffffffffu, bb, off);
        }
        if (lane == 0) { sred[0] = a; ssred[0] = bb; }
    }
    __syncthreads();

    const float mean = sred[0] * (1.0f / DM);
    const float var  = ssred[0] * (1.0f / DM) - mean * mean;
    const float inv  = rsqrtf(var + 1e-6f);

    const float4 gv = ((const float4*)g)[threadIdx.x];
    const float4 bv = ((const float4*)be)[threadIdx.x];
    float o[4];
    o[0] = (v.x - mean) * inv * gv.x + bv.x;
    o[1] = (v.y - mean) * inv * gv.y + bv.y;
    o[2] = (v.z - mean) * inv * gv.z + bv.z;
    o[3] = (v.w - mean) * inv * gv.w + bv.w;
    float4 of = { o[0], o[1], o[2], o[3] };
    ((float4*)(out + (size_t)row * DM))[threadIdx.x] = of;

    if (BFOUT) {
        const size_t base2 = (size_t)row * (DM / 2) + threadIdx.x * 2;
        bf16 h[4], l[4];
        #pragma unroll
        for (int j = 0; j < 4; j++) {
            h[j] = __float2bfloat16(o[j]);
            l[j] = __float2bfloat16(o[j] - __bfloat162float(h[j]));
        }
        ((__nv_bfloat162*)oh)[base2]     = __halves2bfloat162(h[0], h[1]);
        ((__nv_bfloat162*)oh)[base2 + 1] = __halves2bfloat162(h[2], h[3]);
        ((__nv_bfloat162*)ol)[base2]     = __halves2bfloat162(l[0], l[1]);
        ((__nv_bfloat162*)ol)[base2 + 1] = __halves2bfloat162(l[2], l[3]);
    }
}

// ---------------------------------------------------------------------------
// Launch
// ---------------------------------------------------------------------------
extern "C" void kernel_launch(void* const* d_in, const int* in_sizes, int n_in,
                              void* d_out, int out_size)
{
    const float* x   = (const float*)d_in[0];
    const float* wq  = (const float*)d_in[2];
    const float* bq  = (const float*)d_in[3];
    const float* wk  = (const float*)d_in[4];
    const float* bk  = (const float*)d_in[5];
    const float* wv  = (const float*)d_in[6];
    const float* bv  = (const float*)d_in[7];
    const float* wo  = (const float*)d_in[8];
    const float* bo  = (const float*)d_in[9];
    const float* g1  = (const float*)d_in[10];
    const float* be1 = (const float*)d_in[11];
    const float* w1  = (const float*)d_in[12];
    const float* b1  = (const float*)d_in[13];
    const float* w2  = (const float*)d_in[14];
    const float* b2  = (const float*)d_in[15];
    const float* g2  = (const float*)d_in[16];
    const float* be2 = (const float*)d_in[17];
    float* out = (float*)d_out;

    float *res1, *out1, *res2;
    cudaGetSymbolAddress((void**)&res1, g_res1);
    cudaGetSymbolAddress((void**)&out1, g_out1);
    cudaGetSymbolAddress((void**)&res2, g_res2);

    __half *qf, *kf, *vf;
    cudaGetSymbolAddress((void**)&qf, g_qf);
    cudaGetSymbolAddress((void**)&kf, g_kf);
    cudaGetSymbolAddress((void**)&vf, g_vf);

    bf16 *xh, *xl, *ch, *cl, *o1h, *o1l, *hh, *hl;
    bf16 *wqh, *wql, *wkh, *wkl, *wvh, *wvl, *woh, *wol, *w1h, *w1l, *w2h, *w2l;
    cudaGetSymbolAddress((void**)&xh,  g_xh);   cudaGetSymbolAddress((void**)&xl,  g_xl);
    cudaGetSymbolAddress((void**)&ch,  g_ch);   cudaGetSymbolAddress((void**)&cl,  g_cl);
    cudaGetSymbolAddress((void**)&o1h, g_o1h);  cudaGetSymbolAddress((void**)&o1l, g_o1l);
    cudaGetSymbolAddress((void**)&hh,  g_hh);   cudaGetSymbolAddress((void**)&hl,  g_hl);
    cudaGetSymbolAddress((void**)&wqh, g_wqh);  cudaGetSymbolAddress((void**)&wql, g_wql);
    cudaGetSymbolAddress((void**)&wkh, g_wkh);  cudaGetSymbolAddress((void**)&wkl, g_wkl);
    cudaGetSymbolAddress((void**)&wvh, g_wvh);  cudaGetSymbolAddress((void**)&wvl, g_wvl);
    cudaGetSymbolAddress((void**)&woh, g_woh);  cudaGetSymbolAddress((void**)&wol, g_wol);
    cudaGetSymbolAddress((void**)&w1h, g_w1h);  cudaGetSymbolAddress((void**)&w1l, g_w1l);
    cudaGetSymbolAddress((void**)&w2h, g_w2h);  cudaGetSymbolAddress((void**)&w2l, g_w2l);

    cudaFuncSetAttribute(flash2, cudaFuncAttributeMaxDynamicSharedMemorySize, FLASH2_SMEM);
    cudaFuncSetAttribute((const void*)gemm_mma<0, 2>, cudaFuncAttributeMaxDynamicSharedMemorySize, GEMM_SMEM_BYTES);
    cudaFuncSetAttribute((const void*)gemm_mma<1, 1>, cudaFuncAttributeMaxDynamicSharedMemorySize, GEMM_SMEM_BYTES);
    cudaFuncSetAttribute((const void*)gemm_mma<2, 0>, cudaFuncAttributeMaxDynamicSharedMemorySize, GEMM_SMEM_BYTES);

    const dim3 blk(256);
    const dim3 tblk(32, 8);

    // Operand prep
    tsplit_kernel<<<dim3(DM / 32,  DM / 32),  tblk>>>(wq, wqh, wql, DM, DM);
    tsplit_kernel<<<dim3(DM / 32,  DM / 32),  tblk>>>(wk, wkh, wkl, DM, DM);
    tsplit_kernel<<<dim3(DM / 32,  DM / 32),  tblk>>>(wv, wvh, wvl, DM, DM);
    tsplit_kernel<<<dim3(DM / 32,  DM / 32),  tblk>>>(wo, woh, wol, DM, DM);
    tsplit_kernel<<<dim3(DFF_ / 32, DM / 32), tblk>>>(w1, w1h, w1l, DM, DFF_);
    tsplit_kernel<<<dim3(DM / 32, DFF_ / 32), tblk>>>(w2, w2h, w2l, DFF_, DM);
    split_kernel<<<(NTOK * DM / 4 + 255) / 256, blk>>>(x, xh, xl, NTOK * DM / 4);

    const dim3 gD(DM / 128,   NTOK / 128);
    const dim3 gF(DFF_ / 128, NTOK / 128);

    // Q/K/V projections (f16 out for flash)
    gemm_mma<0, 2><<<gD, blk, GEMM_SMEM_BYTES>>>(xh, xl, wqh, wql, bq, nullptr, nullptr, (bf16*)qf, nullptr, NTOK, DM, DM);
    gemm_mma<0, 2><<<gD, blk, GEMM_SMEM_BYTES>>>(xh, xl, wkh, wkl, bk, nullptr, nullptr, (bf16*)kf, nullptr, NTOK, DM, DM);
    gemm_mma<0, 2><<<gD, blk, GEMM_SMEM_BYTES>>>(xh, xl, wvh, wvl, bv, nullptr, nullptr, (bf16*)vf, nullptr, NTOK, DM, DM);

    // Causal flash attention -> ctx (bf16 hi/lo)
    flash2<<<dim3(SEQ / 128, 2 * NH), blk, FLASH2_SMEM>>>(qf, kf, vf, ch, cl);

    // res1 = x + ctx @ wo + bo ; out1 = LN(res1) (+ hi/lo)
    gemm_mma<2, 0><<<gD, blk, GEMM_SMEM_BYTES>>>(ch, cl, woh, wol, bo, x, res1, nullptr, nullptr, NTOK, DM, DM);
    ln_kernel<true><<<NTOK, blk>>>(res1, g1, be1, out1, o1h, o1l);

    // hid = relu(out1 @ w1 + b1)  (bf16 hi/lo only)
    gemm_mma<1, 1><<<gF, blk, GEMM_SMEM_BYTES>>>(o1h, o1l, w1h, w1l, b1, nullptr, nullptr, hh, hl, NTOK, DFF_, DM);

    // res2 = out1 + hid @ w2 + b2 ; out = LN(res2)
    gemm_mma<2, 0><<<gD, blk, GEMM_SMEM_BYTES>>>(hh, hl, w2h, w2l, b2, out1, res2, nullptr, nullptr, NTOK, DM, DFF_);
    ln_kernel<false><<<NTOK, blk>>>(res2, g2, be2, out, nullptr, nullptr);
}